// round 1
// baseline (speedup 1.0000x reference)
#include <cuda_runtime.h>
#include <cuda_fp16.h>
#include <stdint.h>

// Problem constants
#define IC    384
#define OCC   384
#define NB    32
#define IH    64
#define IW    64
#define OH    32
#define OW    32
#define KTOT  (IC * 9)          // 3456
#define NWEI  (OCC * IC * 9)    // 1327104
#define NTOT  (NB * OH * OW)    // 32768

// GEMM tiling
#define BM    128
#define BN    128
#define BK    32
#define APAD  40                // halves per A smem row (80B, 16B aligned, CF frag reads)
#define BPAD  34                // halves per B smem row (68B, CF STS)
#define NKB   (KTOT / BK)       // 108

// Scratch (device globals: allocation-free contract)
__device__ float  g_alpha;
__device__ float  g_part[256];
__device__ __half g_wq[(size_t)OCC * KTOT];   // [oc][tap*384 + ic], fp16 in {-1,0,+1}

// ---------------------------------------------------------------------------
// Stage 1: deterministic partial reduction of |w|
// ---------------------------------------------------------------------------
__global__ void abssum_part(const float* __restrict__ w) {
    __shared__ float sm[256];
    const int tid = threadIdx.x;
    float s = 0.f;
    for (int i = blockIdx.x * 256 + tid; i < NWEI; i += 256 * 256)
        s += fabsf(w[i]);
    sm[tid] = s;
    __syncthreads();
    #pragma unroll
    for (int o = 128; o > 0; o >>= 1) {
        if (tid < o) sm[tid] += sm[tid + o];
        __syncthreads();
    }
    if (tid == 0) g_part[blockIdx.x] = sm[0];
}

__global__ void abssum_fin() {
    __shared__ float sm[256];
    const int tid = threadIdx.x;
    sm[tid] = g_part[tid];
    __syncthreads();
    #pragma unroll
    for (int o = 128; o > 0; o >>= 1) {
        if (tid < o) sm[tid] += sm[tid + o];
        __syncthreads();
    }
    if (tid == 0) g_alpha = sm[0] / (float)NWEI;
}

// ---------------------------------------------------------------------------
// Stage 2: ternary quantize + layout transform OIHW -> [oc][tap*384+ic] fp16
// ---------------------------------------------------------------------------
__global__ void quantize_w(const float* __restrict__ w) {
    const int j = blockIdx.x * 256 + threadIdx.x;
    if (j >= NWEI) return;
    const float thr = 0.001f * g_alpha;
    const int oc  = j / KTOT;
    const int r   = j - oc * KTOT;
    const int tap = r / IC;
    const int ic  = r - tap * IC;
    const float wv = w[oc * KTOT + ic * 9 + tap];     // OIHW linear
    const float q = (wv > thr) ? 1.f : ((wv < -thr) ? -1.f : 0.f);
    g_wq[j] = __float2half_rn(q);
}

// ---------------------------------------------------------------------------
// Stage 3: implicit-GEMM conv, mma.sync m16n8k16 f16->f32
//   C[oc][n] = sum_k Wq[oc][k] * X[k][n],  k = tap*384+ic, n = b*1024+oy*32+ox
// ---------------------------------------------------------------------------
__device__ __forceinline__ void gather_regs(
    const float* __restrict__ xb, int kb, int oy, int ox, int kr0,
    int tid, int oc0, float bv[16], uint4 av[2])
{
    // tap is constant within a k-block (384 % 32 == 0, 12 blocks per tap)
    const int tap = kb / 12;
    const int icb = (kb - tap * 12) << 5;
    const int kh  = tap / 3;
    const int kw  = tap - kh * 3;
    const int iy  = 2 * oy - 1 + kh;
    const int ix  = 2 * ox - 1 + kw;
    const bool inb = ((unsigned)iy < IH) && ((unsigned)ix < IW);
    const float* p = xb + (size_t)(icb + kr0) * (IH * IW) + iy * IW + ix;
    #pragma unroll
    for (int i = 0; i < 16; i++)
        bv[i] = inb ? p[(size_t)i * 2 * IH * IW] : 0.f;

    const int k0 = kb << 5;
    #pragma unroll
    for (int j = 0; j < 2; j++) {
        const int idx = tid + (j << 8);
        const int m = idx >> 2, quad = idx & 3;
        av[j] = *reinterpret_cast<const uint4*>(
            g_wq + (size_t)(oc0 + m) * KTOT + k0 + quad * 8);
    }
}

__device__ __forceinline__ void sts_regs(
    __half* __restrict__ As, __half* __restrict__ Bs,
    const float bv[16], const uint4 av[2], int nn, int kr0, int tid)
{
    #pragma unroll
    for (int i = 0; i < 16; i++)
        Bs[nn * BPAD + kr0 + 2 * i] = __float2half_rn(bv[i]);
    #pragma unroll
    for (int j = 0; j < 2; j++) {
        const int idx = tid + (j << 8);
        const int m = idx >> 2, quad = idx & 3;
        *reinterpret_cast<uint4*>(As + m * APAD + quad * 8) = av[j];
    }
}

__device__ __forceinline__ void compute_block(
    const __half* __restrict__ As, const __half* __restrict__ Bs,
    float acc[4][4][4], int wm, int wn, int lane)
{
    const int g  = lane >> 2;
    const int tq = lane & 3;
    #pragma unroll
    for (int step = 0; step < 2; step++) {
        const int kk = step * 16 + tq * 2;
        uint32_t a[4][4], bb[4][2];
        #pragma unroll
        for (int ms = 0; ms < 4; ms++) {
            const __half* pA = As + (wm * 64 + ms * 16 + g) * APAD + kk;
            a[ms][0] = *reinterpret_cast<const uint32_t*>(pA);
            a[ms][1] = *reinterpret_cast<const uint32_t*>(pA + 8 * APAD);
            a[ms][2] = *reinterpret_cast<const uint32_t*>(pA + 8);
            a[ms][3] = *reinterpret_cast<const uint32_t*>(pA + 8 * APAD + 8);
        }
        #pragma unroll
        for (int ns = 0; ns < 4; ns++) {
            const __half* pB = Bs + (wn * 32 + ns * 8 + g) * BPAD + kk;
            bb[ns][0] = *reinterpret_cast<const uint32_t*>(pB);
            bb[ns][1] = *reinterpret_cast<const uint32_t*>(pB + 8);
        }
        #pragma unroll
        for (int ms = 0; ms < 4; ms++)
            #pragma unroll
            for (int ns = 0; ns < 4; ns++)
                asm volatile(
                    "mma.sync.aligned.m16n8k16.row.col.f32.f16.f16.f32 "
                    "{%0,%1,%2,%3}, {%4,%5,%6,%7}, {%8,%9}, {%0,%1,%2,%3};"
                    : "+f"(acc[ms][ns][0]), "+f"(acc[ms][ns][1]),
                      "+f"(acc[ms][ns][2]), "+f"(acc[ms][ns][3])
                    : "r"(a[ms][0]), "r"(a[ms][1]), "r"(a[ms][2]), "r"(a[ms][3]),
                      "r"(bb[ns][0]), "r"(bb[ns][1]));
    }
}

__global__ __launch_bounds__(256, 2)
void conv_mma(const float* __restrict__ x, const float* __restrict__ bias,
              float* __restrict__ out)
{
    __shared__ __half As[2][BM * APAD];
    __shared__ __half Bs[2][BN * BPAD];

    const int tid  = threadIdx.x;
    const int lane = tid & 31;
    const int wid  = tid >> 5;
    const int wm   = wid >> 2;          // 0..1
    const int wn   = wid & 3;           // 0..3

    const int m_tile = blockIdx.x % 3;  // adjacent bids share the x slab (L2)
    const int n_tile = blockIdx.x / 3;
    const int oc0  = m_tile * BM;
    const int n0   = n_tile * BN;
    const int bimg = n0 >> 10;          // BN=128 divides 1024: tile within one image
    const int pos0 = n0 & 1023;

    // B-gather per-thread invariants
    const int nn  = tid & 127;
    const int kr0 = tid >> 7;           // 0/1
    const int pos = pos0 + nn;
    const int oy  = pos >> 5;
    const int ox  = pos & 31;
    const float* xb = x + (size_t)bimg * IC * IH * IW;

    float acc[4][4][4];
    #pragma unroll
    for (int i = 0; i < 4; i++)
        #pragma unroll
        for (int j = 0; j < 4; j++)
            #pragma unroll
            for (int c = 0; c < 4; c++)
                acc[i][j][c] = 0.f;

    float bv[16];
    uint4 av[2];

    // prologue
    gather_regs(xb, 0, oy, ox, kr0, tid, oc0, bv, av);
    sts_regs(As[0], Bs[0], bv, av, nn, kr0, tid);

    #pragma unroll 1
    for (int kb = 0; kb < NKB; kb++) {
        __syncthreads();
        const int cur = kb & 1;
        const bool more = (kb + 1 < NKB);
        if (more) gather_regs(xb, kb + 1, oy, ox, kr0, tid, oc0, bv, av);
        compute_block(As[cur], Bs[cur], acc, wm, wn, lane);
        if (more) sts_regs(As[cur ^ 1], Bs[cur ^ 1], bv, av, nn, kr0, tid);
    }

    // epilogue: out = alpha*acc + bias   (NCHW: per-batch [oc][pos] row-major)
    const float alpha = g_alpha;
    const int g  = lane >> 2;
    const int tq = lane & 3;
    float* ob = out + (size_t)bimg * OCC * (OH * OW);
    #pragma unroll
    for (int ms = 0; ms < 4; ms++) {
        const int oc_a = oc0 + wm * 64 + ms * 16 + g;
        const int oc_b = oc_a + 8;
        const float ba = bias[oc_a];
        const float bc = bias[oc_b];
        #pragma unroll
        for (int ns = 0; ns < 4; ns++) {
            const int pcol = pos0 + wn * 32 + ns * 8 + tq * 2;
            float2 v0, v1;
            v0.x = alpha * acc[ms][ns][0] + ba;
            v0.y = alpha * acc[ms][ns][1] + ba;
            v1.x = alpha * acc[ms][ns][2] + bc;
            v1.y = alpha * acc[ms][ns][3] + bc;
            *reinterpret_cast<float2*>(ob + (size_t)oc_a * (OH * OW) + pcol) = v0;
            *reinterpret_cast<float2*>(ob + (size_t)oc_b * (OH * OW) + pcol) = v1;
        }
    }
}

// ---------------------------------------------------------------------------
extern "C" void kernel_launch(void* const* d_in, const int* in_sizes, int n_in,
                              void* d_out, int out_size)
{
    (void)in_sizes; (void)n_in; (void)out_size;
    const float* x      = (const float*)d_in[0];
    const float* weight = (const float*)d_in[1];
    const float* bias   = (const float*)d_in[2];
    // d_in[3] = time_emb, d_in[4] = y : unused by the reference
    float* out = (float*)d_out;

    abssum_part<<<256, 256>>>(weight);
    abssum_fin<<<1, 256>>>();
    quantize_w<<<(NWEI + 255) / 256, 256>>>(weight);
    conv_mma<<<(NTOT / BN) * 3, 256>>>(x, bias, out);
}

// round 2
// speedup vs baseline: 1.4437x; 1.4437x over previous
#include <cuda_runtime.h>
#include <cuda_fp16.h>
#include <stdint.h>

// Problem constants
#define IC    384
#define OCC   384
#define NB    32
#define IH    64
#define IW    64
#define OH    32
#define OW    32
#define KTOT  (IC * 9)          // 3456
#define NWEI  (OCC * KTOT)      // 1327104
#define NTOT  (NB * OH * OW)    // 32768

// GEMM tiling
#define BM    128
#define BN    128
#define BK    32
#define NKB   (KTOT / BK)       // 108
#define S     4                 // cp.async pipeline stages
#define ASTR  40                // halves per A smem row (80B: 16B-aligned, LDSM conflict-free)
#define BSTR  136               // halves per B smem row (272B: 16B-aligned, LDSM conflict-free)
#define ABYTES (BM * ASTR * 2)  // 10240
#define BBYTES (BK * BSTR * 2)  // 8704
#define SMEM_TOTAL (S * (ABYTES + BBYTES))  // 75776

#define KWSZ ((size_t)NB * IC * 66 * 32)    // 25952256 halves per kw image

// Scratch (device globals: allocation-free contract)
__device__ float  g_alpha;
__device__ float  g_part[256];
__device__ __half g_wq[(size_t)NKB * OCC * BK];  // [kb][oc][32] ternary fp16
__device__ __half g_xq[3 * KWSZ];                // [kw][b][ic][row 0..65][ox 0..31]

// ---------------------------------------------------------------------------
// Stage 1: deterministic |w| reduction -> alpha
// ---------------------------------------------------------------------------
__global__ void abssum_part(const float* __restrict__ w) {
    __shared__ float sm[256];
    const int tid = threadIdx.x;
    float s = 0.f;
    for (int i = blockIdx.x * 256 + tid; i < NWEI; i += 256 * 256)
        s += fabsf(w[i]);
    sm[tid] = s;
    __syncthreads();
    #pragma unroll
    for (int o = 128; o > 0; o >>= 1) {
        if (tid < o) sm[tid] += sm[tid + o];
        __syncthreads();
    }
    if (tid == 0) g_part[blockIdx.x] = sm[0];
}

__global__ void abssum_fin() {
    __shared__ float sm[256];
    const int tid = threadIdx.x;
    sm[tid] = g_part[tid];
    __syncthreads();
    #pragma unroll
    for (int o = 128; o > 0; o >>= 1) {
        if (tid < o) sm[tid] += sm[tid + o];
        __syncthreads();
    }
    if (tid == 0) g_alpha = sm[0] / (float)NWEI;
}

// ---------------------------------------------------------------------------
// Stage 2a: ternary quantize, layout OIHW -> [kb][oc][32] fp16
// ---------------------------------------------------------------------------
__global__ void quantize_w(const float* __restrict__ w) {
    const int j = blockIdx.x * 256 + threadIdx.x;
    if (j >= NWEI) return;
    const float thr = 0.001f * g_alpha;
    const int oc  = j / KTOT;
    const int r   = j - oc * KTOT;
    const int tap = r / IC;
    const int ic  = r - tap * IC;
    const float wv = w[oc * KTOT + ic * 9 + tap];     // OIHW linear
    const float q = (wv > thr) ? 1.f : ((wv < -thr) ? -1.f : 0.f);
    const int kb = tap * 12 + (ic >> 5);
    g_wq[((size_t)kb * OCC + oc) * BK + (ic & 31)] = __float2half_rn(q);
}

// ---------------------------------------------------------------------------
// Stage 2b: x fp32 -> fp16, deinterleaved by kw tap, padded halo rows.
//   xq[kw][bc][row][ox] = x[bc][row-1][2*ox-1+kw]  (OOB -> 0), row 0 is iy=-1
// ---------------------------------------------------------------------------
__global__ void prep_x(const float* __restrict__ x) {
    const int idx = blockIdx.x * 256 + threadIdx.x;
    const int t = idx & 15;             // handles ox pair (2t, 2t+1)
    const int r = idx >> 4;             // row id over NB*IC*65
    if (r >= NB * IC * 65) return;
    const int iy = r % 65 - 1;          // -1..63
    const int bc = r / 65;              // b*IC + ic
    const size_t orow = ((size_t)bc * 66 + (iy + 1)) * 32 + 2 * t;

    __half2 h0, h1, h2;
    if (iy < 0) {
        h0 = h1 = h2 = __floats2half2_rn(0.f, 0.f);
    } else {
        const float* xr = x + ((size_t)bc * IH + iy) * IW;
        const float4 v = *reinterpret_cast<const float4*>(xr + 4 * t);
        const float prev = (t > 0) ? xr[4 * t - 1] : 0.f;
        h0 = __floats2half2_rn(prev, v.y);   // kw=0: ix = 2ox-1
        h1 = __floats2half2_rn(v.x,  v.z);   // kw=1: ix = 2ox
        h2 = __floats2half2_rn(v.y,  v.w);   // kw=2: ix = 2ox+1
    }
    *reinterpret_cast<__half2*>(g_xq + 0 * KWSZ + orow) = h0;
    *reinterpret_cast<__half2*>(g_xq + 1 * KWSZ + orow) = h1;
    *reinterpret_cast<__half2*>(g_xq + 2 * KWSZ + orow) = h2;
}

// ---------------------------------------------------------------------------
// Stage 3: implicit-GEMM conv, cp.async pipeline + ldmatrix + mma.sync
// ---------------------------------------------------------------------------
__device__ __forceinline__ void cp16(uint32_t dst, const void* src) {
    asm volatile("cp.async.cg.shared.global [%0], [%1], 16;\n"
                 :: "r"(dst), "l"(src) : "memory");
}

__global__ __launch_bounds__(256, 2)
void conv_mma2(const float* __restrict__ bias, float* __restrict__ out)
{
    extern __shared__ char smem_raw[];
    const uint32_t sbase = (uint32_t)__cvta_generic_to_shared(smem_raw);

    const int tid  = threadIdx.x;
    const int lane = tid & 31;
    const int wid  = tid >> 5;
    const int wm   = wid >> 2;          // 0..1
    const int wn   = wid & 3;           // 0..3

    const int m_tile = blockIdx.x % 3;  // adjacent bids share the B slab (L2)
    const int n_tile = blockIdx.x / 3;
    const int oc0  = m_tile * BM;
    const int n0   = n_tile * BN;
    const int bimg = n0 >> 10;
    const int pos0 = n0 & 1023;
    const int oy0  = pos0 >> 5;

    // ---- per-thread cp.async source/dest invariants ----
    // A: chunk = tid + 256j : m = chunk>>2, c = chunk&3  (dense coalesced LDG)
    size_t   aoff[2];
    uint32_t adst[2];
    #pragma unroll
    for (int j = 0; j < 2; j++) {
        const int chunk = tid + (j << 8);
        const int m = chunk >> 2, c = chunk & 3;
        aoff[j] = (size_t)(oc0 + m) * BK + c * 8;
        adst[j] = sbase + (uint32_t)(m * ASTR + c * 8) * 2;
    }
    // B: slot = tid + 256j : kB = slot>>4, nc = slot&15
    size_t   boff[2];
    uint32_t bdst[2];
    #pragma unroll
    for (int j = 0; j < 2; j++) {
        const int slot = tid + (j << 8);
        const int kB = slot >> 4, nc = slot & 15;
        const int oyc = oy0 + (nc >> 2);
        boff[j] = ((size_t)(bimg * IC + kB) * 66 + 2 * oyc) * 32 + (nc & 3) * 8;
        bdst[j] = sbase + (uint32_t)(S * ABYTES) + (uint32_t)(kB * BSTR + nc * 8) * 2;
    }

    // ---- ldmatrix per-lane invariants ----
    const int arow  = wm * 64 + ((lane >> 3) & 1) * 8 + (lane & 7);
    const int acol  = (lane >> 4) * 8;
    const int brow  = ((lane >> 3) & 1) * 8 + (lane & 7);
    const int bcolh = wn * 32 + (lane >> 4) * 8;

    float acc[4][4][4];
    #pragma unroll
    for (int i = 0; i < 4; i++)
        #pragma unroll
        for (int j = 0; j < 4; j++)
            #pragma unroll
            for (int c = 0; c < 4; c++)
                acc[i][j][c] = 0.f;

    auto issue = [&](int kb, int s) {
        const int tap = kb / 12;                 // 0..8
        const int icb = (kb - tap * 12) << 5;
        const int kh  = tap / 3;
        const int kw  = tap - kh * 3;
        const __half* wsrc = g_wq + (size_t)kb * (OCC * BK);
        const __half* xsrc = g_xq + (size_t)kw * KWSZ + (size_t)icb * (66 * 32) + kh * 32;
        const uint32_t as = (uint32_t)(s * ABYTES);
        const uint32_t bs = (uint32_t)(s * BBYTES);
        cp16(adst[0] + as, wsrc + aoff[0]);
        cp16(adst[1] + as, wsrc + aoff[1]);
        cp16(bdst[0] + bs, xsrc + boff[0]);
        cp16(bdst[1] + bs, xsrc + boff[1]);
        asm volatile("cp.async.commit_group;\n" ::: "memory");
    };

    auto compute = [&](int s) {
        const uint32_t aB = sbase + (uint32_t)(s * ABYTES);
        const uint32_t bB = sbase + (uint32_t)(S * ABYTES + s * BBYTES);
        #pragma unroll
        for (int step = 0; step < 2; step++) {
            uint32_t a[4][4];
            #pragma unroll
            for (int ms = 0; ms < 4; ms++) {
                const uint32_t addr = aB + (uint32_t)(((arow + ms * 16) * ASTR) + step * 16 + acol) * 2;
                asm volatile("ldmatrix.sync.aligned.m8n8.x4.shared.b16 {%0,%1,%2,%3}, [%4];\n"
                             : "=r"(a[ms][0]), "=r"(a[ms][1]), "=r"(a[ms][2]), "=r"(a[ms][3])
                             : "r"(addr));
            }
            uint32_t b[2][4];
            #pragma unroll
            for (int nb = 0; nb < 2; nb++) {
                const uint32_t addr = bB + (uint32_t)((step * 16 + brow) * BSTR + bcolh + nb * 16) * 2;
                asm volatile("ldmatrix.sync.aligned.m8n8.x4.trans.shared.b16 {%0,%1,%2,%3}, [%4];\n"
                             : "=r"(b[nb][0]), "=r"(b[nb][1]), "=r"(b[nb][2]), "=r"(b[nb][3])
                             : "r"(addr));
            }
            #pragma unroll
            for (int ms = 0; ms < 4; ms++)
                #pragma unroll
                for (int ns = 0; ns < 4; ns++)
                    asm volatile(
                        "mma.sync.aligned.m16n8k16.row.col.f32.f16.f16.f32 "
                        "{%0,%1,%2,%3}, {%4,%5,%6,%7}, {%8,%9}, {%0,%1,%2,%3};\n"
                        : "+f"(acc[ms][ns][0]), "+f"(acc[ms][ns][1]),
                          "+f"(acc[ms][ns][2]), "+f"(acc[ms][ns][3])
                        : "r"(a[ms][0]), "r"(a[ms][1]), "r"(a[ms][2]), "r"(a[ms][3]),
                          "r"(b[ns >> 1][(ns & 1) * 2]), "r"(b[ns >> 1][(ns & 1) * 2 + 1]));
        }
    };

    // prologue: fill S-1 stages
    issue(0, 0); issue(1, 1); issue(2, 2);

    #pragma unroll 1
    for (int kb = 0; kb < NKB; kb++) {
        asm volatile("cp.async.wait_group %0;\n" :: "n"(S - 2) : "memory");
        __syncthreads();
        if (kb + (S - 1) < NKB) issue(kb + (S - 1), (kb + (S - 1)) & (S - 1));
        compute(kb & (S - 1));
    }

    // epilogue: out = alpha*acc + bias   (NCHW per-batch [oc][pos] row-major)
    const float alpha = g_alpha;
    const int g  = lane >> 2;
    const int tq = lane & 3;
    float* ob = out + (size_t)bimg * OCC * (OH * OW);
    #pragma unroll
    for (int ms = 0; ms < 4; ms++) {
        const int oc_a = oc0 + wm * 64 + ms * 16 + g;
        const int oc_b = oc_a + 8;
        const float ba = bias[oc_a];
        const float bc = bias[oc_b];
        #pragma unroll
        for (int ns = 0; ns < 4; ns++) {
            const int pcol = pos0 + wn * 32 + ns * 8 + tq * 2;
            float2 v0, v1;
            v0.x = alpha * acc[ms][ns][0] + ba;
            v0.y = alpha * acc[ms][ns][1] + ba;
            v1.x = alpha * acc[ms][ns][2] + bc;
            v1.y = alpha * acc[ms][ns][3] + bc;
            *reinterpret_cast<float2*>(ob + (size_t)oc_a * (OH * OW) + pcol) = v0;
            *reinterpret_cast<float2*>(ob + (size_t)oc_b * (OH * OW) + pcol) = v1;
        }
    }
}

// ---------------------------------------------------------------------------
extern "C" void kernel_launch(void* const* d_in, const int* in_sizes, int n_in,
                              void* d_out, int out_size)
{
    (void)in_sizes; (void)n_in; (void)out_size;
    const float* x      = (const float*)d_in[0];
    const float* weight = (const float*)d_in[1];
    const float* bias   = (const float*)d_in[2];
    float* out = (float*)d_out;

    static int smem_set = 0;
    if (!smem_set) {
        cudaFuncSetAttribute(conv_mma2, cudaFuncAttributeMaxDynamicSharedMemorySize, SMEM_TOTAL);
        smem_set = 1;
    }

    abssum_part<<<256, 256>>>(weight);
    abssum_fin<<<1, 256>>>();
    quantize_w<<<(NWEI + 255) / 256, 256>>>(weight);
    prep_x<<<(NB * IC * 65 * 16 + 255) / 256, 256>>>(x);
    conv_mma2<<<(NTOT / BN) * 3, 256, SMEM_TOTAL>>>(bias, out);
}

// round 3
// speedup vs baseline: 1.4441x; 1.0003x over previous
#include <cuda_runtime.h>
#include <cuda_fp16.h>
#include <stdint.h>

// Problem constants
#define IC    384
#define OCC   384
#define NB    32
#define IH    64
#define IW    64
#define OH    32
#define OW    32
#define KTOT  (IC * 9)          // 3456
#define NWEI  (OCC * KTOT)      // 1327104
#define NTOT  (NB * OH * OW)    // 32768

// GEMM tiling
#define BM    128
#define BN    128
#define BK    32
#define NKB   (KTOT / BK)       // 108
#define S     4                 // cp.async pipeline stages
#define ASTR  40                // halves per A smem row (80B: 16B-aligned, LDSM conflict-free)
#define BSTR  136               // halves per B smem row (272B: 16B-aligned, LDSM conflict-free)
#define ABYTES (BM * ASTR * 2)  // 10240
#define BBYTES (BK * BSTR * 2)  // 8704
#define SMEM_TOTAL (S * (ABYTES + BBYTES))  // 75776

#define KWSZ ((size_t)NB * IC * 66 * 32)    // 25952256 halves per kw image

// Scratch (device globals: allocation-free contract)
__device__ float  g_alpha;
__device__ float  g_part[256];
__device__ __half g_wq[(size_t)NKB * OCC * BK];  // [kb][oc][32] ternary fp16
__device__ __half g_xq[3 * KWSZ];                // [kw][b][ic][row 0..65][ox 0..31]

// ---------------------------------------------------------------------------
// Stage 1: deterministic |w| reduction -> alpha
// ---------------------------------------------------------------------------
__global__ void abssum_part(const float* __restrict__ w) {
    __shared__ float sm[256];
    const int tid = threadIdx.x;
    float s = 0.f;
    for (int i = blockIdx.x * 256 + tid; i < NWEI; i += 256 * 256)
        s += fabsf(w[i]);
    sm[tid] = s;
    __syncthreads();
    #pragma unroll
    for (int o = 128; o > 0; o >>= 1) {
        if (tid < o) sm[tid] += sm[tid + o];
        __syncthreads();
    }
    if (tid == 0) g_part[blockIdx.x] = sm[0];
}

__global__ void abssum_fin() {
    __shared__ float sm[256];
    const int tid = threadIdx.x;
    sm[tid] = g_part[tid];
    __syncthreads();
    #pragma unroll
    for (int o = 128; o > 0; o >>= 1) {
        if (tid < o) sm[tid] += sm[tid + o];
        __syncthreads();
    }
    if (tid == 0) g_alpha = sm[0] / (float)NWEI;
}

// ---------------------------------------------------------------------------
// Stage 2a: ternary quantize, layout OIHW -> [kb][oc][32] fp16
// ---------------------------------------------------------------------------
__global__ void quantize_w(const float* __restrict__ w) {
    const int j = blockIdx.x * 256 + threadIdx.x;
    if (j >= NWEI) return;
    const float thr = 0.001f * g_alpha;
    const int oc  = j / KTOT;
    const int r   = j - oc * KTOT;
    const int tap = r / IC;
    const int ic  = r - tap * IC;
    const float wv = w[oc * KTOT + ic * 9 + tap];     // OIHW linear
    const float q = (wv > thr) ? 1.f : ((wv < -thr) ? -1.f : 0.f);
    const int kb = tap * 12 + (ic >> 5);
    g_wq[((size_t)kb * OCC + oc) * BK + (ic & 31)] = __float2half_rn(q);
}

// ---------------------------------------------------------------------------
// Stage 2b: x fp32 -> fp16, deinterleaved by kw tap, padded halo rows.
//   xq[kw][bc][row][ox] = x[bc][row-1][2*ox-1+kw]  (OOB -> 0), row 0 is iy=-1
// ---------------------------------------------------------------------------
__global__ void prep_x(const float* __restrict__ x) {
    const int idx = blockIdx.x * 256 + threadIdx.x;
    const int t = idx & 15;             // handles ox pair (2t, 2t+1)
    const int r = idx >> 4;             // row id over NB*IC*65
    if (r >= NB * IC * 65) return;
    const int iy = r % 65 - 1;          // -1..63
    const int bc = r / 65;              // b*IC + ic
    const size_t orow = ((size_t)bc * 66 + (iy + 1)) * 32 + 2 * t;

    __half2 h0, h1, h2;
    if (iy < 0) {
        h0 = h1 = h2 = __floats2half2_rn(0.f, 0.f);
    } else {
        const float* xr = x + ((size_t)bc * IH + iy) * IW;
        const float4 v = *reinterpret_cast<const float4*>(xr + 4 * t);
        const float prev = (t > 0) ? xr[4 * t - 1] : 0.f;
        h0 = __floats2half2_rn(prev, v.y);   // kw=0: ix = 2ox-1
        h1 = __floats2half2_rn(v.x,  v.z);   // kw=1: ix = 2ox
        h2 = __floats2half2_rn(v.y,  v.w);   // kw=2: ix = 2ox+1
    }
    *reinterpret_cast<__half2*>(g_xq + 0 * KWSZ + orow) = h0;
    *reinterpret_cast<__half2*>(g_xq + 1 * KWSZ + orow) = h1;
    *reinterpret_cast<__half2*>(g_xq + 2 * KWSZ + orow) = h2;
}

// ---------------------------------------------------------------------------
// Stage 3: implicit-GEMM conv, cp.async pipeline + ldmatrix + mma.sync
// ---------------------------------------------------------------------------
__device__ __forceinline__ void cp16(uint32_t dst, const void* src) {
    asm volatile("cp.async.cg.shared.global [%0], [%1], 16;\n"
                 :: "r"(dst), "l"(src) : "memory");
}

__global__ __launch_bounds__(256, 2)
void conv_mma2(const float* __restrict__ bias, float* __restrict__ out)
{
    extern __shared__ char smem_raw[];
    const uint32_t sbase = (uint32_t)__cvta_generic_to_shared(smem_raw);

    const int tid  = threadIdx.x;
    const int lane = tid & 31;
    const int wid  = tid >> 5;
    const int wm   = wid >> 2;          // 0..1
    const int wn   = wid & 3;           // 0..3

    const int m_tile = blockIdx.x % 3;  // adjacent bids share the B slab (L2)
    const int n_tile = blockIdx.x / 3;
    const int oc0  = m_tile * BM;
    const int n0   = n_tile * BN;
    const int bimg = n0 >> 10;
    const int pos0 = n0 & 1023;
    const int oy0  = pos0 >> 5;

    // ---- per-thread cp.async source/dest invariants ----
    // A: chunk = tid + 256j : m = chunk>>2, c = chunk&3  (dense coalesced LDG)
    size_t   aoff[2];
    uint32_t adst[2];
    #pragma unroll
    for (int j = 0; j < 2; j++) {
        const int chunk = tid + (j << 8);
        const int m = chunk >> 2, c = chunk & 3;
        aoff[j] = (size_t)(oc0 + m) * BK + c * 8;
        adst[j] = sbase + (uint32_t)(m * ASTR + c * 8) * 2;
    }
    // B: slot = tid + 256j : kB = slot>>4, nc = slot&15
    size_t   boff[2];
    uint32_t bdst[2];
    #pragma unroll
    for (int j = 0; j < 2; j++) {
        const int slot = tid + (j << 8);
        const int kB = slot >> 4, nc = slot & 15;
        const int oyc = oy0 + (nc >> 2);
        boff[j] = ((size_t)(bimg * IC + kB) * 66 + 2 * oyc) * 32 + (nc & 3) * 8;
        bdst[j] = sbase + (uint32_t)(S * ABYTES) + (uint32_t)(kB * BSTR + nc * 8) * 2;
    }

    // ---- ldmatrix per-lane invariants ----
    const int arow  = wm * 64 + ((lane >> 3) & 1) * 8 + (lane & 7);
    const int acol  = (lane >> 4) * 8;
    const int brow  = ((lane >> 3) & 1) * 8 + (lane & 7);
    const int bcolh = wn * 32 + (lane >> 4) * 8;

    float acc[4][4][4];
    #pragma unroll
    for (int i = 0; i < 4; i++)
        #pragma unroll
        for (int j = 0; j < 4; j++)
            #pragma unroll
            for (int c = 0; c < 4; c++)
                acc[i][j][c] = 0.f;

    auto issue = [&](int kb, int s) {
        const int tap = kb / 12;                 // 0..8
        const int icb = (kb - tap * 12) << 5;
        const int kh  = tap / 3;
        const int kw  = tap - kh * 3;
        const __half* wsrc = g_wq + (size_t)kb * (OCC * BK);
        const __half* xsrc = g_xq + (size_t)kw * KWSZ + (size_t)icb * (66 * 32) + kh * 32;
        const uint32_t as = (uint32_t)(s * ABYTES);
        const uint32_t bs = (uint32_t)(s * BBYTES);
        cp16(adst[0] + as, wsrc + aoff[0]);
        cp16(adst[1] + as, wsrc + aoff[1]);
        cp16(bdst[0] + bs, xsrc + boff[0]);
        cp16(bdst[1] + bs, xsrc + boff[1]);
        asm volatile("cp.async.commit_group;\n" ::: "memory");
    };

    auto compute = [&](int s) {
        const uint32_t aB = sbase + (uint32_t)(s * ABYTES);
        const uint32_t bB = sbase + (uint32_t)(S * ABYTES + s * BBYTES);
        #pragma unroll
        for (int step = 0; step < 2; step++) {
            uint32_t a[4][4];
            #pragma unroll
            for (int ms = 0; ms < 4; ms++) {
                const uint32_t addr = aB + (uint32_t)(((arow + ms * 16) * ASTR) + step * 16 + acol) * 2;
                asm volatile("ldmatrix.sync.aligned.m8n8.x4.shared.b16 {%0,%1,%2,%3}, [%4];\n"
                             : "=r"(a[ms][0]), "=r"(a[ms][1]), "=r"(a[ms][2]), "=r"(a[ms][3])
                             : "r"(addr));
            }
            uint32_t b[2][4];
            #pragma unroll
            for (int nb = 0; nb < 2; nb++) {
                const uint32_t addr = bB + (uint32_t)((step * 16 + brow) * BSTR + bcolh + nb * 16) * 2;
                asm volatile("ldmatrix.sync.aligned.m8n8.x4.trans.shared.b16 {%0,%1,%2,%3}, [%4];\n"
                             : "=r"(b[nb][0]), "=r"(b[nb][1]), "=r"(b[nb][2]), "=r"(b[nb][3])
                             : "r"(addr));
            }
            #pragma unroll
            for (int ms = 0; ms < 4; ms++)
                #pragma unroll
                for (int ns = 0; ns < 4; ns++)
                    asm volatile(
                        "mma.sync.aligned.m16n8k16.row.col.f32.f16.f16.f32 "
                        "{%0,%1,%2,%3}, {%4,%5,%6,%7}, {%8,%9}, {%0,%1,%2,%3};\n"
                        : "+f"(acc[ms][ns][0]), "+f"(acc[ms][ns][1]),
                          "+f"(acc[ms][ns][2]), "+f"(acc[ms][ns][3])
                        : "r"(a[ms][0]), "r"(a[ms][1]), "r"(a[ms][2]), "r"(a[ms][3]),
                          "r"(b[ns >> 1][(ns & 1) * 2]), "r"(b[ns >> 1][(ns & 1) * 2 + 1]));
        }
    };

    // prologue: fill S-1 stages
    issue(0, 0); issue(1, 1); issue(2, 2);

    #pragma unroll 1
    for (int kb = 0; kb < NKB; kb++) {
        asm volatile("cp.async.wait_group %0;\n" :: "n"(S - 2) : "memory");
        __syncthreads();
        if (kb + (S - 1) < NKB) issue(kb + (S - 1), (kb + (S - 1)) & (S - 1));
        compute(kb & (S - 1));
    }

    // epilogue: out = alpha*acc + bias   (NCHW per-batch [oc][pos] row-major)
    const float alpha = g_alpha;
    const int g  = lane >> 2;
    const int tq = lane & 3;
    float* ob = out + (size_t)bimg * OCC * (OH * OW);
    #pragma unroll
    for (int ms = 0; ms < 4; ms++) {
        const int oc_a = oc0 + wm * 64 + ms * 16 + g;
        const int oc_b = oc_a + 8;
        const float ba = bias[oc_a];
        const float bc = bias[oc_b];
        #pragma unroll
        for (int ns = 0; ns < 4; ns++) {
            const int pcol = pos0 + wn * 32 + ns * 8 + tq * 2;
            float2 v0, v1;
            v0.x = alpha * acc[ms][ns][0] + ba;
            v0.y = alpha * acc[ms][ns][1] + ba;
            v1.x = alpha * acc[ms][ns][2] + bc;
            v1.y = alpha * acc[ms][ns][3] + bc;
            *reinterpret_cast<float2*>(ob + (size_t)oc_a * (OH * OW) + pcol) = v0;
            *reinterpret_cast<float2*>(ob + (size_t)oc_b * (OH * OW) + pcol) = v1;
        }
    }
}

// ---------------------------------------------------------------------------
extern "C" void kernel_launch(void* const* d_in, const int* in_sizes, int n_in,
                              void* d_out, int out_size)
{
    (void)in_sizes; (void)n_in; (void)out_size;
    const float* x      = (const float*)d_in[0];
    const float* weight = (const float*)d_in[1];
    const float* bias   = (const float*)d_in[2];
    float* out = (float*)d_out;

    static int smem_set = 0;
    if (!smem_set) {
        cudaFuncSetAttribute(conv_mma2, cudaFuncAttributeMaxDynamicSharedMemorySize, SMEM_TOTAL);
        smem_set = 1;
    }

    abssum_part<<<256, 256>>>(weight);
    abssum_fin<<<1, 256>>>();
    quantize_w<<<(NWEI + 255) / 256, 256>>>(weight);
    prep_x<<<(NB * IC * 65 * 16 + 255) / 256, 256>>>(x);
    conv_mma2<<<(NTOT / BN) * 3, 256, SMEM_TOTAL>>>(bias, out);
}